// round 5
// baseline (speedup 1.0000x reference)
#include <cuda_runtime.h>

// QLSTM closed form:
//   qgate(x, p)[:, w] = prod_{j<=w} cos(p[j,1]) * cos(y[:,j] + p[j,0])
// LSTM cell + residual + layernorm; sequential over T only, independent per row.

#define TT 128
#define BB 256
#define DD 64
#define HH 10
#define G4 40   // 4 gates * H
#define WROW (DD + HH)   // 74: row stride of Wg

// Layout: pre[b][t][ch]  (row-contiguous so each scan warp streams 20KB)
__device__ float g_pre[BB * TT * G4];

typedef unsigned long long ull;

__device__ __forceinline__ float tanh_fast(float x) {
    float y;
    asm("tanh.approx.f32 %0, %1;" : "=f"(y) : "f"(x));
    return y;
}
__device__ __forceinline__ float sig_fast(float x) {
    return fmaf(0.5f, tanh_fast(0.5f * x), 0.5f);
}
__device__ __forceinline__ ull fma2(ull a, ull b, ull c) {
    ull d;
    asm("fma.rn.f32x2 %0, %1, %2, %3;" : "=l"(d) : "l"(a), "l"(b), "l"(c));
    return d;
}
__device__ __forceinline__ ull mul2(ull a, ull b) {
    ull d;
    asm("mul.rn.f32x2 %0, %1, %2;" : "=l"(d) : "l"(a), "l"(b));
    return d;
}
__device__ __forceinline__ ull add2(ull a, ull b) {
    ull d;
    asm("add.rn.f32x2 %0, %1, %2;" : "=l"(d) : "l"(a), "l"(b));
    return d;
}
__device__ __forceinline__ void unpack2(float& lo, float& hi, ull v) {
    asm("mov.b64 {%0, %1}, %2;" : "=f"(lo), "=f"(hi) : "l"(v));
}
#define ONE2_BITS 0x3F8000003F800000ull

// ---------------------------------------------------------------------------
// Kernel 1: pre[b][t][:] = fold_bias + x[t,b,:] @ Wg[:, :64]^T
// fold_bias = b_g[w] + p_g[w,0] + sum_j lnb_j * Whh_g[w,j]  (cos phase folded)
// Register-resident weights, shfl x-broadcast, no shared in the hot loop.
// One warp handles one batch col b and 8 consecutive t (contiguous store).
// ---------------------------------------------------------------------------
__global__ void __launch_bounds__(128) k_pre(
    const float* __restrict__ x,
    const float* __restrict__ Wf, const float* __restrict__ bf, const float* __restrict__ pf,
    const float* __restrict__ Wi, const float* __restrict__ bi, const float* __restrict__ pi,
    const float* __restrict__ Wu, const float* __restrict__ bu, const float* __restrict__ pu,
    const float* __restrict__ Wo, const float* __restrict__ bo, const float* __restrict__ po,
    const float* __restrict__ lnb_)
{
    int tid  = threadIdx.x;
    int warp = tid >> 5, l = tid & 31;
    int wg   = blockIdx.x * 4 + warp;     // 0..4095
    int b    = wg & (BB - 1);
    int tg   = wg >> 8;                    // 0..15
    int tbase = tg * 8;

    // channel 0 = l (gate l/10, wire l%10; l=30,31 -> gate3 wires 0,1)
    // channel 1 = 32+l for l<8 (gate3, wires 2..9)
    int g0 = l / 10, w0 = l - g0 * 10;
    const float* Wg0 = (g0 == 0) ? Wf : (g0 == 1) ? Wi : (g0 == 2) ? Wu : Wo;
    const float* bg0 = (g0 == 0) ? bf : (g0 == 1) ? bi : (g0 == 2) ? bu : bo;
    const float* pg0 = (g0 == 0) ? pf : (g0 == 1) ? pi : (g0 == 2) ? pu : po;

    float wa[DD];
    #pragma unroll
    for (int d = 0; d < DD; d++) wa[d] = Wg0[w0 * WROW + d];
    float bias0 = bg0[w0] + pg0[w0 * 3 + 0];
    #pragma unroll
    for (int j = 0; j < HH; j++)
        bias0 = fmaf(lnb_[j], Wg0[w0 * WROW + DD + j], bias0);

    float wb[DD];
    float bias1 = 0.f;
    int w1 = 2 + l;
    #pragma unroll
    for (int d = 0; d < DD; d++) wb[d] = (l < 8) ? Wo[w1 * WROW + d] : 0.f;
    if (l < 8) {
        bias1 = bo[w1] + po[w1 * 3 + 0];
        #pragma unroll
        for (int j = 0; j < HH; j++)
            bias1 = fmaf(lnb_[j], Wo[w1 * WROW + DD + j], bias1);
    }

    for (int i = 0; i < 8; i++) {
        int t = tbase + i;
        const float* xr = x + ((size_t)t * BB + b) * DD;
        float x0 = xr[l];
        float x1 = xr[l + 32];

        float a0 = bias0, a0b = 0.f;
        float a1 = bias1, a1b = 0.f;
        #pragma unroll
        for (int d = 0; d < 32; d += 2) {
            float xd0 = __shfl_sync(0xffffffffu, x0, d);
            float xd1 = __shfl_sync(0xffffffffu, x0, d + 1);
            a0  = fmaf(xd0, wa[d], a0);
            a0b = fmaf(xd1, wa[d + 1], a0b);
            a1  = fmaf(xd0, wb[d], a1);
            a1b = fmaf(xd1, wb[d + 1], a1b);
        }
        #pragma unroll
        for (int d = 0; d < 32; d += 2) {
            float xd0 = __shfl_sync(0xffffffffu, x1, d);
            float xd1 = __shfl_sync(0xffffffffu, x1, d + 1);
            a0  = fmaf(xd0, wa[32 + d], a0);
            a0b = fmaf(xd1, wa[32 + d + 1], a0b);
            a1  = fmaf(xd0, wb[32 + d], a1);
            a1b = fmaf(xd1, wb[32 + d + 1], a1b);
        }
        float* pr = g_pre + ((size_t)b * TT + t) * G4;
        pr[l] = a0 + a0b;
        if (l < 8) pr[32 + l] = a1 + a1b;
    }
}

// ---------------------------------------------------------------------------
// Kernel 2: sequential scan. One warp per batch row, 4 warps/block, 64 blocks.
// Packed-f32x2 gate math; hr-carry (mu/rsqrt off-chain); depth-2 prefetch.
// Shared q-exchange layout (per warp, per parity): floats
//   [0..19]  : (q_f[w]-1, q_i[w]-1) interleaved -> 16B loads give packed pairs
//   [20..39] : (q_u[w]-1, q_o[w]-1) interleaved
// ---------------------------------------------------------------------------
__global__ void __launch_bounds__(128) k_scan(
    const float* __restrict__ Wf, const float* __restrict__ pf,
    const float* __restrict__ Wi, const float* __restrict__ pi,
    const float* __restrict__ Wu, const float* __restrict__ pu,
    const float* __restrict__ Wo, const float* __restrict__ po,
    const float* __restrict__ lng_, const float* __restrict__ lnb_,
    float* __restrict__ out)
{
    __shared__ __align__(16) float qs[4][2][48];

    int tid  = threadIdx.x;
    int warp = tid >> 5, l = tid & 31;
    int row  = blockIdx.x * 4 + warp;

    int g0 = l / 10, w0 = l - g0 * 10;
    const float* Wg0 = (g0 == 0) ? Wf : (g0 == 1) ? Wi : (g0 == 2) ? Wu : Wo;
    const float* Pg0 = (g0 == 0) ? pf : (g0 == 1) ? pi : (g0 == 2) ? pu : po;

    float cth1_0 = cosf(Pg0[w0 * 3 + 1]);
    float whh0[HH], sw0 = 0.f;
    #pragma unroll
    for (int j = 0; j < HH; j++) {
        whh0[j] = Wg0[w0 * WROW + DD + j] * lng_[j];
        sw0 += whh0[j];
    }
    int pos0 = (g0 < 2) ? (2 * w0 + g0) : (20 + 2 * w0 + (g0 - 2));

    int w1 = 2 + l;
    float cth1_1 = 0.f, sw1 = 0.f;
    float whh1[HH];
    #pragma unroll
    for (int j = 0; j < HH; j++) whh1[j] = 0.f;
    if (l < 8) {
        cth1_1 = cosf(po[w1 * 3 + 1]);
        #pragma unroll
        for (int j = 0; j < HH; j++) {
            whh1[j] = Wo[w1 * WROW + DD + j] * lng_[j];
            sw1 += whh1[j];
        }
    }
    int pos1 = 20 + 2 * w1 + 1;

    float lng_l = 0.f, lnb_l = 0.f;
    if (l < HH) { lng_l = lng_[l]; lnb_l = lnb_[l]; }

    // packed lane masks: mj[j] = (l >= j) ? {1,1} : {0,0}
    ull mj[HH];
    #pragma unroll
    for (int j = 0; j < HH; j++) mj[j] = (l >= j) ? ONE2_BITS : 0ull;
    const ull ONE2 = ONE2_BITS;

    float hr[HH];
    #pragma unroll
    for (int j = 0; j < HH; j++) hr[j] = 0.f;
    float mu = 0.f, rs = 0.f;
    float creg = 0.f, hown = 0.f;

    const float* prow = g_pre + (size_t)row * TT * G4;
    float preA0 = prow[l];
    float preA1 = (l < 8) ? prow[32 + l] : 0.f;
    float preB0 = prow[G4 + l];
    float preB1 = (l < 8) ? prow[G4 + 32 + l] : 0.f;

    float* outp = out + (size_t)row * HH;
    const size_t ostride = (size_t)BB * HH;

    #pragma unroll 2
    for (int t = 0; t < TT; t++) {
        // prefetch t+2 (clamped)
        int tn = (t + 2 < TT) ? t + 2 : TT - 1;
        const float* pn = prow + (size_t)tn * G4;
        float preC0 = pn[l];
        float preC1 = (l < 8) ? pn[32 + l] : 0.f;

        // dot over hr; mu correction via sw; rs folds at the end
        float a0 = 0.f, a1 = 0.f, a2 = 0.f, a3 = 0.f;
        float c0 = 0.f, c1 = 0.f, c2 = 0.f, c3 = 0.f;
        a0 = fmaf(hr[0], whh0[0], a0);  c0 = fmaf(hr[0], whh1[0], c0);
        a1 = fmaf(hr[1], whh0[1], a1);  c1 = fmaf(hr[1], whh1[1], c1);
        a2 = fmaf(hr[2], whh0[2], a2);  c2 = fmaf(hr[2], whh1[2], c2);
        a3 = fmaf(hr[3], whh0[3], a3);  c3 = fmaf(hr[3], whh1[3], c3);
        a0 = fmaf(hr[4], whh0[4], a0);  c0 = fmaf(hr[4], whh1[4], c0);
        a1 = fmaf(hr[5], whh0[5], a1);  c1 = fmaf(hr[5], whh1[5], c1);
        a2 = fmaf(hr[6], whh0[6], a2);  c2 = fmaf(hr[6], whh1[6], c2);
        a3 = fmaf(hr[7], whh0[7], a3);  c3 = fmaf(hr[7], whh1[7], c3);
        a0 = fmaf(hr[8], whh0[8], a0);  c0 = fmaf(hr[8], whh1[8], c0);
        a1 = fmaf(hr[9], whh0[9], a1);  c1 = fmaf(hr[9], whh1[9], c1);
        float dot0 = (a0 + a1) + (a2 + a3);
        float dot1 = (c0 + c1) + (c2 + c3);
        float y0 = fmaf(rs, fmaf(-mu, sw0, dot0), preA0);
        float y1 = fmaf(rs, fmaf(-mu, sw1, dot1), preA1);

        // q - 1  (store shifted so consumer mask-fma needs no SEL)
        float qm1_0 = fmaf(cth1_0, __cosf(y0), -1.f);
        float qm1_1 = fmaf(cth1_1, __cosf(y1), -1.f);

        int par = t & 1;
        qs[warp][par][pos0] = qm1_0;
        if (l < 8) qs[warp][par][pos1] = qm1_1;
        __syncwarp();

        // load packed (q-1) pairs: 10x 16B loads -> 20 packed values
        const ulonglong2* qv = (const ulonglong2*)&qs[warp][par][0];
        ulonglong2 f01 = qv[0], f23 = qv[1], f45 = qv[2], f67 = qv[3], f89 = qv[4];
        ulonglong2 u01 = qv[5], u23 = qv[6], u45 = qv[7], u67 = qv[8], u89 = qv[9];

        // masked: v_j = 1 + m_j*(q_j - 1)
        ull vf0 = fma2(mj[0], f01.x, ONE2), vu0 = fma2(mj[0], u01.x, ONE2);
        ull vf1 = fma2(mj[1], f01.y, ONE2), vu1 = fma2(mj[1], u01.y, ONE2);
        ull vf2 = fma2(mj[2], f23.x, ONE2), vu2 = fma2(mj[2], u23.x, ONE2);
        ull vf3 = fma2(mj[3], f23.y, ONE2), vu3 = fma2(mj[3], u23.y, ONE2);
        ull vf4 = fma2(mj[4], f45.x, ONE2), vu4 = fma2(mj[4], u45.x, ONE2);
        ull vf5 = fma2(mj[5], f45.y, ONE2), vu5 = fma2(mj[5], u45.y, ONE2);
        ull vf6 = fma2(mj[6], f67.x, ONE2), vu6 = fma2(mj[6], u67.x, ONE2);
        ull vf7 = fma2(mj[7], f67.y, ONE2), vu7 = fma2(mj[7], u67.y, ONE2);
        ull vf8 = fma2(mj[8], f89.x, ONE2), vu8 = fma2(mj[8], u89.x, ONE2);
        ull vf9 = fma2(mj[9], f89.y, ONE2), vu9 = fma2(mj[9], u89.y, ONE2);

        // product tree (2-wide, both pairs in flight)
        ull pf01 = mul2(vf0, vf1), pu01 = mul2(vu0, vu1);
        ull pf23 = mul2(vf2, vf3), pu23 = mul2(vu2, vu3);
        ull pf45 = mul2(vf4, vf5), pu45 = mul2(vu4, vu5);
        ull pf67 = mul2(vf6, vf7), pu67 = mul2(vu6, vu7);
        ull pf89 = mul2(vf8, vf9), pu89 = mul2(vu8, vu9);
        ull pf03 = mul2(pf01, pf23), pu03 = mul2(pu01, pu23);
        ull pf47 = mul2(pf45, pf67), pu47 = mul2(pu45, pu67);
        ull pFI  = mul2(mul2(pf03, pf47), pf89);
        ull pUO  = mul2(mul2(pu03, pu47), pu89);

        float pF, pI, pU, pO;
        unpack2(pF, pI, pFI);
        unpack2(pU, pO, pUO);

        float fg = sig_fast(pF);
        float ig = sig_fast(pI);
        float gg = tanh_fast(pU);
        float og = sig_fast(pO);
        creg = fmaf(fg, creg, ig * gg);
        float hval = fmaf(og, tanh_fast(creg), hown);

        // gather raw h into every lane
        #pragma unroll
        for (int j = 0; j < HH; j++) hr[j] = __shfl_sync(0xffffffffu, hval, j);

        // LN stats off the next step's critical path (hr feeds dot directly)
        float sA = 0.f, sB = 0.f, qA = 0.f, qB = 0.f;
        #pragma unroll
        for (int j = 0; j < HH; j += 2) {
            sA += hr[j];
            sB += hr[j + 1];
            qA = fmaf(hr[j],     hr[j],     qA);
            qB = fmaf(hr[j + 1], hr[j + 1], qB);
        }
        mu = (sA + sB) * 0.1f;
        rs = rsqrtf(fmaf(-mu, mu, (qA + qB) * 0.1f) + 1e-5f);
        hown = fmaf((hval - mu) * rs, lng_l, lnb_l);

        if (l < HH)
            outp[l] = hown;
        outp += ostride;

        preA0 = preB0; preA1 = preB1;
        preB0 = preC0; preB1 = preC1;
    }

    if (l < HH) {
        out[(size_t)TT * BB * HH + (size_t)row * HH + l]           = hown;
        out[(size_t)TT * BB * HH + (size_t)BB * HH + row * HH + l] = creg;
    }
}

extern "C" void kernel_launch(void* const* d_in, const int* in_sizes, int n_in,
                              void* d_out, int out_size)
{
    const float* x   = (const float*)d_in[0];
    const float* Wf  = (const float*)d_in[1];
    const float* bf  = (const float*)d_in[2];
    const float* pf  = (const float*)d_in[3];
    const float* Wi  = (const float*)d_in[4];
    const float* bi  = (const float*)d_in[5];
    const float* pi_ = (const float*)d_in[6];
    const float* Wu  = (const float*)d_in[7];
    const float* bu  = (const float*)d_in[8];
    const float* pu  = (const float*)d_in[9];
    const float* Wo  = (const float*)d_in[10];
    const float* bo  = (const float*)d_in[11];
    const float* po  = (const float*)d_in[12];
    const float* lng = (const float*)d_in[13];
    const float* lnb = (const float*)d_in[14];

    k_pre<<<1024, 128>>>(x, Wf, bf, pf, Wi, bi, pi_, Wu, bu, pu, Wo, bo, po, lnb);
    k_scan<<<BB / 4, 128>>>(Wf, pf, Wi, pi_, Wu, pu, Wo, po, lng, lnb, (float*)d_out);
}